// round 2
// baseline (speedup 1.0000x reference)
#include <cuda_runtime.h>
#include <cuda_bf16.h>
#include <math.h>

// ---------------- problem constants ----------------
#define NB     32
#define SEQ    197
#define DMODEL 768
#define NHEAD  12
#define DHEAD  64
#define LAYERS 12
#define MLPD   3072
#define OUTD   1000
#define PPATCH 196
#define IN_DIM 768
#define NS     (NB * SEQ)       // 6304 tokens
#define NP     (NB * PPATCH)    // 6272 patches
#define SP     200              // padded score row stride (16B-aligned float4 rows)

// ---------------- device scratch (static, no allocations) ----------------
__device__ float g_patches[NP * IN_DIM];            // 19.3 MB
__device__ float g_x[NS * DMODEL];                  // residual stream
__device__ float g_h[NS * DMODEL];                  // LN output
__device__ float g_q[NS * DMODEL];
__device__ float g_k[NS * DMODEL];
__device__ float g_v[NS * DMODEL];
__device__ float g_sc[NB * NHEAD * SEQ * SP];       // 60.5 MB padded scores
__device__ float g_mlp[NS * MLPD];                  // 77.4 MB (also token buf)

// ---------------- patchify: [N,C,H,W] -> [N*196, 768] ----------------
__global__ void __launch_bounds__(256)
patchify_kernel(const float* __restrict__ img)
{
    int idx = blockIdx.x * 256 + threadIdx.x;
    if (idx >= NP * IN_DIM) return;
    int t = idx / IN_DIM;
    int e = idx - t * IN_DIM;    // 768 is NOT a power of 2 — must use true mod
    int n = t / PPATCH;
    int p = t - n * PPATCH;
    int py = p / 14, px = p - py * 14;
    int c  = e >> 8;             // IN_DIM decomposes as c*256 + ph*16 + pw
    int r  = e & 255;
    int ph = r >> 4, pw = r & 15;
    g_patches[idx] = img[(((size_t)n * 3 + c) * 224 + (py * 16 + ph)) * 224 + px * 16 + pw];
}

// ---------------- assemble x = [cls ; tokens] + pos ----------------
__global__ void __launch_bounds__(256)
assemble_kernel(const float* __restrict__ tokens, const float* __restrict__ cls,
                const float* __restrict__ pos)
{
    int idx = blockIdx.x * 256 + threadIdx.x;
    if (idx >= NS * DMODEL) return;
    int t = idx / DMODEL;
    int d = idx - t * DMODEL;    // true mod (768 not a power of 2)
    int n = t / SEQ;
    int s = t - n * SEQ;
    float v = (s == 0) ? cls[d] : tokens[((size_t)(n * PPATCH + s - 1)) * DMODEL + d];
    g_x[idx] = v + pos[s * DMODEL + d];
}

// ---------------- generic 128x128x8 SGEMM, C = A@B + bias (+epilogue) ----------------
// EPI: 0 = bias only, 1 = bias + exact GELU, 2 = bias + residual add
template<int EPI>
__global__ void __launch_bounds__(256)
sgemm128(const float* __restrict__ A, const float* __restrict__ B,
         const float* __restrict__ bias, const float* __restrict__ res,
         float* __restrict__ C, int M, int N, int K)
{
    __shared__ float As[8][128];
    __shared__ float Bs[8][128];
    const int tid = threadIdx.x;
    const int bm = blockIdx.y * 128;
    const int bn = blockIdx.x * 128;

    const int arow = tid >> 1;
    const int acol = (tid & 1) * 4;
    const int brow = tid >> 5;
    const int bcol = (tid & 31) * 4;
    const int tr = (tid >> 4) * 8;
    const int tc = (tid & 15) * 8;

    float acc[8][8];
    #pragma unroll
    for (int i = 0; i < 8; i++)
        #pragma unroll
        for (int j = 0; j < 8; j++) acc[i][j] = 0.f;

    const bool aval = (bm + arow) < M;
    const float* Aptr = A + (size_t)(bm + arow) * K + acol;
    const int gcol = bn + bcol;

    for (int k0 = 0; k0 < K; k0 += 8) {
        float4 av = make_float4(0.f, 0.f, 0.f, 0.f);
        if (aval) av = *(const float4*)(Aptr + k0);
        As[acol + 0][arow] = av.x;
        As[acol + 1][arow] = av.y;
        As[acol + 2][arow] = av.z;
        As[acol + 3][arow] = av.w;

        float4 bv = make_float4(0.f, 0.f, 0.f, 0.f);
        const float* Bp = B + (size_t)(k0 + brow) * N + gcol;
        if (gcol + 3 < N) {
            bv = *(const float4*)Bp;
        } else {
            if (gcol + 0 < N) bv.x = Bp[0];
            if (gcol + 1 < N) bv.y = Bp[1];
            if (gcol + 2 < N) bv.z = Bp[2];
        }
        Bs[brow][bcol + 0] = bv.x;
        Bs[brow][bcol + 1] = bv.y;
        Bs[brow][bcol + 2] = bv.z;
        Bs[brow][bcol + 3] = bv.w;
        __syncthreads();

        #pragma unroll
        for (int k = 0; k < 8; k++) {
            float ra[8], rb[8];
            #pragma unroll
            for (int i = 0; i < 8; i++) ra[i] = As[k][tr + i];
            #pragma unroll
            for (int j = 0; j < 8; j++) rb[j] = Bs[k][tc + j];
            #pragma unroll
            for (int i = 0; i < 8; i++)
                #pragma unroll
                for (int j = 0; j < 8; j++)
                    acc[i][j] = fmaf(ra[i], rb[j], acc[i][j]);
        }
        __syncthreads();
    }

    #pragma unroll
    for (int i = 0; i < 8; i++) {
        int row = bm + tr + i;
        if (row >= M) continue;
        #pragma unroll
        for (int j = 0; j < 8; j++) {
            int col = bn + tc + j;
            if (col >= N) continue;
            float vv = acc[i][j] + bias[col];
            if (EPI == 1) vv = 0.5f * vv * (1.f + erff(vv * 0.70710678118654752f));
            if (EPI == 2) vv += res[(size_t)row * N + col];
            C[(size_t)row * N + col] = vv;
        }
    }
}

// ---------------- LayerNorm (block per token) ----------------
__global__ void __launch_bounds__(256)
ln_kernel(const float* __restrict__ x, const float* __restrict__ g,
          const float* __restrict__ b, float* __restrict__ o)
{
    int row = blockIdx.x;
    int tid = threadIdx.x;
    const float* xr = x + (size_t)row * DMODEL;
    float v0 = xr[tid], v1 = xr[tid + 256], v2 = xr[tid + 512];

    __shared__ float red[10];
    float s = v0 + v1 + v2;
    #pragma unroll
    for (int of = 16; of; of >>= 1) s += __shfl_xor_sync(~0u, s, of);
    if ((tid & 31) == 0) red[tid >> 5] = s;
    __syncthreads();
    if (tid == 0) {
        float t = 0.f;
        #pragma unroll
        for (int i = 0; i < 8; i++) t += red[i];
        red[8] = t * (1.f / 768.f);
    }
    __syncthreads();
    float mu = red[8];
    float d0 = v0 - mu, d1 = v1 - mu, d2 = v2 - mu;
    float q = d0 * d0 + d1 * d1 + d2 * d2;
    #pragma unroll
    for (int of = 16; of; of >>= 1) q += __shfl_xor_sync(~0u, q, of);
    if ((tid & 31) == 0) red[tid >> 5] = q;
    __syncthreads();
    if (tid == 0) {
        float t = 0.f;
        #pragma unroll
        for (int i = 0; i < 8; i++) t += red[i];
        red[9] = rsqrtf(t * (1.f / 768.f) + 1e-5f);
    }
    __syncthreads();
    float inv = red[9];
    float* orow = o + (size_t)row * DMODEL;
    orow[tid]       = d0 * inv * g[tid]       + b[tid];
    orow[tid + 256] = d1 * inv * g[tid + 256] + b[tid + 256];
    orow[tid + 512] = d2 * inv * g[tid + 512] + b[tid + 512];
}

// ---------------- per-head QKV projection (64x64 block GEMM) ----------------
__global__ void __launch_bounds__(256)
qkv_kernel(const float* __restrict__ h,
           const float* __restrict__ Wq, const float* __restrict__ Wk, const float* __restrict__ Wv,
           const float* __restrict__ bq, const float* __restrict__ bk, const float* __restrict__ bv,
           float* __restrict__ q, float* __restrict__ k, float* __restrict__ v)
{
    int t0 = blockIdx.x * 64;
    int hh = blockIdx.y;
    int z  = blockIdx.z;
    const float* W  = (z == 0) ? Wq : (z == 1) ? Wk : Wv;
    const float* bb = (z == 0) ? bq : (z == 1) ? bk : bv;
    float* out      = (z == 0) ? q  : (z == 1) ? k  : v;
    W  += hh * 64 * 64;
    bb += hh * 64;

    __shared__ float Xs[64][64];   // [d][token]
    __shared__ float Ws[64][64];   // [d][e]
    int tid = threadIdx.x;
    #pragma unroll
    for (int r = 0; r < 4; r++) {
        int row = (tid >> 4) + r * 16;
        int col = (tid & 15) * 4;
        int tok = t0 + row;
        float4 xv = make_float4(0.f, 0.f, 0.f, 0.f);
        if (tok < NS) xv = *(const float4*)(h + (size_t)tok * DMODEL + hh * 64 + col);
        Xs[col + 0][row] = xv.x; Xs[col + 1][row] = xv.y;
        Xs[col + 2][row] = xv.z; Xs[col + 3][row] = xv.w;
        float4 wv = *(const float4*)(W + row * 64 + col);
        Ws[row][col + 0] = wv.x; Ws[row][col + 1] = wv.y;
        Ws[row][col + 2] = wv.z; Ws[row][col + 3] = wv.w;
    }
    __syncthreads();

    int trr = (tid >> 4) * 4;
    int tcc = (tid & 15) * 4;
    float acc[4][4] = {};
    #pragma unroll
    for (int d = 0; d < 64; d++) {
        float ra[4], rb[4];
        #pragma unroll
        for (int i = 0; i < 4; i++) ra[i] = Xs[d][trr + i];
        #pragma unroll
        for (int j = 0; j < 4; j++) rb[j] = Ws[d][tcc + j];
        #pragma unroll
        for (int i = 0; i < 4; i++)
            #pragma unroll
            for (int j = 0; j < 4; j++)
                acc[i][j] = fmaf(ra[i], rb[j], acc[i][j]);
    }
    #pragma unroll
    for (int i = 0; i < 4; i++) {
        int tok = t0 + trr + i;
        if (tok >= NS) continue;
        #pragma unroll
        for (int j = 0; j < 4; j++)
            out[(size_t)tok * DMODEL + hh * 64 + tcc + j] = acc[i][j] + bb[tcc + j];
    }
}

// ---------------- scores = Q K^T / 8, batched over (n,h) ----------------
__global__ void __launch_bounds__(256)
scores_kernel(const float* __restrict__ q, const float* __restrict__ k,
              float* __restrict__ sc)
{
    int q0 = blockIdx.x * 64;
    int k0 = blockIdx.y * 64;
    int b  = blockIdx.z;
    int n  = b / NHEAD, hh = b - n * NHEAD;

    __shared__ float Qs[64][64];   // [e][q]
    __shared__ float Ks[64][64];   // [e][k]
    int tid = threadIdx.x;
    #pragma unroll
    for (int r = 0; r < 4; r++) {
        int row = (tid >> 4) + r * 16;
        int col = (tid & 15) * 4;
        int qt = q0 + row, kt = k0 + row;
        float4 qv = make_float4(0.f, 0.f, 0.f, 0.f);
        float4 kv = make_float4(0.f, 0.f, 0.f, 0.f);
        if (qt < SEQ) qv = *(const float4*)(q + (size_t)(n * SEQ + qt) * DMODEL + hh * 64 + col);
        if (kt < SEQ) kv = *(const float4*)(k + (size_t)(n * SEQ + kt) * DMODEL + hh * 64 + col);
        Qs[col + 0][row] = qv.x; Qs[col + 1][row] = qv.y;
        Qs[col + 2][row] = qv.z; Qs[col + 3][row] = qv.w;
        Ks[col + 0][row] = kv.x; Ks[col + 1][row] = kv.y;
        Ks[col + 2][row] = kv.z; Ks[col + 3][row] = kv.w;
    }
    __syncthreads();

    int tr = (tid >> 4) * 4;
    int tc = (tid & 15) * 4;
    float acc[4][4] = {};
    #pragma unroll
    for (int e = 0; e < 64; e++) {
        float ra[4], rb[4];
        #pragma unroll
        for (int i = 0; i < 4; i++) ra[i] = Qs[e][tr + i];
        #pragma unroll
        for (int j = 0; j < 4; j++) rb[j] = Ks[e][tc + j];
        #pragma unroll
        for (int i = 0; i < 4; i++)
            #pragma unroll
            for (int j = 0; j < 4; j++)
                acc[i][j] = fmaf(ra[i], rb[j], acc[i][j]);
    }
    #pragma unroll
    for (int i = 0; i < 4; i++) {
        int qi = q0 + tr + i;
        if (qi >= SEQ) continue;
        #pragma unroll
        for (int j = 0; j < 4; j++) {
            int kj = k0 + tc + j;
            if (kj < SEQ)
                sc[((size_t)b * SEQ + qi) * SP + kj] = acc[i][j] * 0.125f;
        }
    }
}

// ---------------- softmax (warp per row of 197) ----------------
__global__ void __launch_bounds__(256)
softmax_kernel(float* __restrict__ sc)
{
    int warp = (blockIdx.x * 256 + threadIdx.x) >> 5;
    int lane = threadIdx.x & 31;
    if (warp >= NB * NHEAD * SEQ) return;
    float* row = sc + (size_t)warp * SP;

    float mx = -1e30f;
    for (int i = lane; i < SEQ; i += 32) mx = fmaxf(mx, row[i]);
    #pragma unroll
    for (int of = 16; of; of >>= 1) mx = fmaxf(mx, __shfl_xor_sync(~0u, mx, of));

    float sum = 0.f;
    for (int i = lane; i < SEQ; i += 32) {
        float e = expf(row[i] - mx);
        row[i] = e;
        sum += e;
    }
    #pragma unroll
    for (int of = 16; of; of >>= 1) sum += __shfl_xor_sync(~0u, sum, of);
    float inv = 1.f / sum;
    for (int i = lane; i < SEQ; i += 32) row[i] *= inv;
}

// ---------------- O = attn @ V, fused residual add into x ----------------
__global__ void __launch_bounds__(256)
av_kernel(const float* __restrict__ sc, const float* __restrict__ v,
          float* __restrict__ x)
{
    int q0 = blockIdx.x * 64;
    int b  = blockIdx.y;
    int n  = b / NHEAD, hh = b - n * NHEAD;

    __shared__ float As[64][64];   // [k][q]
    __shared__ float Vs[64][64];   // [k][e]
    int tid = threadIdx.x;
    int tr = (tid >> 4) * 4;
    int tc = (tid & 15) * 4;
    float acc[4][4] = {};

    for (int k0 = 0; k0 < SEQ; k0 += 64) {
        #pragma unroll
        for (int r = 0; r < 4; r++) {
            int row = (tid >> 4) + r * 16;
            int col = (tid & 15) * 4;
            // attention tile (row = query, col = key)
            float4 avv = make_float4(0.f, 0.f, 0.f, 0.f);
            int qt = q0 + row;
            if (qt < SEQ) {
                const float* p = sc + ((size_t)b * SEQ + qt) * SP + k0 + col;
                if (k0 + col + 3 < SEQ) {
                    avv = *(const float4*)p;
                } else {
                    if (k0 + col + 0 < SEQ) avv.x = p[0];
                    if (k0 + col + 1 < SEQ) avv.y = p[1];
                    if (k0 + col + 2 < SEQ) avv.z = p[2];
                }
            }
            As[col + 0][row] = avv.x; As[col + 1][row] = avv.y;
            As[col + 2][row] = avv.z; As[col + 3][row] = avv.w;
            // V tile (row = key, col = e)
            float4 vv = make_float4(0.f, 0.f, 0.f, 0.f);
            int kt = k0 + row;
            if (kt < SEQ) vv = *(const float4*)(v + (size_t)(n * SEQ + kt) * DMODEL + hh * 64 + col);
            Vs[row][col + 0] = vv.x; Vs[row][col + 1] = vv.y;
            Vs[row][col + 2] = vv.z; Vs[row][col + 3] = vv.w;
        }
        __syncthreads();
        #pragma unroll
        for (int kk = 0; kk < 64; kk++) {
            float ra[4], rb[4];
            #pragma unroll
            for (int i = 0; i < 4; i++) ra[i] = As[kk][tr + i];
            #pragma unroll
            for (int j = 0; j < 4; j++) rb[j] = Vs[kk][tc + j];
            #pragma unroll
            for (int i = 0; i < 4; i++)
                #pragma unroll
                for (int j = 0; j < 4; j++)
                    acc[i][j] = fmaf(ra[i], rb[j], acc[i][j]);
        }
        __syncthreads();
    }
    #pragma unroll
    for (int i = 0; i < 4; i++) {
        int qi = q0 + tr + i;
        if (qi >= SEQ) continue;
        #pragma unroll
        for (int j = 0; j < 4; j++) {
            size_t idx = (size_t)(n * SEQ + qi) * DMODEL + hh * 64 + tc + j;
            x[idx] += acc[i][j];
        }
    }
}

// ---------------- classification head + softmax ----------------
__global__ void __launch_bounds__(256)
head_kernel(const float* __restrict__ x, const float* __restrict__ Wh,
            const float* __restrict__ bh, float* __restrict__ out)
{
    __shared__ float xs[DMODEL];
    __shared__ float lg[OUTD];
    __shared__ float red[256];
    int n = blockIdx.x, tid = threadIdx.x;
    for (int i = tid; i < DMODEL; i += 256) xs[i] = x[(size_t)n * SEQ * DMODEL + i];
    __syncthreads();
    for (int o = tid; o < OUTD; o += 256) {
        float a = bh[o];
        for (int kk = 0; kk < DMODEL; kk++)
            a = fmaf(xs[kk], Wh[(size_t)kk * OUTD + o], a);
        lg[o] = a;
    }
    __syncthreads();
    float m = -1e30f;
    for (int o = tid; o < OUTD; o += 256) m = fmaxf(m, lg[o]);
    red[tid] = m; __syncthreads();
    for (int s = 128; s; s >>= 1) { if (tid < s) red[tid] = fmaxf(red[tid], red[tid + s]); __syncthreads(); }
    float mx = red[0]; __syncthreads();
    float sm = 0.f;
    for (int o = tid; o < OUTD; o += 256) sm += expf(lg[o] - mx);
    red[tid] = sm; __syncthreads();
    for (int s = 128; s; s >>= 1) { if (tid < s) red[tid] += red[tid + s]; __syncthreads(); }
    float inv = 1.f / red[0];
    __syncthreads();
    for (int o = tid; o < OUTD; o += 256)
        out[(size_t)n * OUTD + o] = expf(lg[o] - mx) * inv;
}

// ---------------- host orchestration ----------------
extern "C" void kernel_launch(void* const* d_in, const int* in_sizes, int n_in,
                              void* d_out, int out_size)
{
    const float* images   = (const float*)d_in[0];
    const float* W_map    = (const float*)d_in[1];
    const float* b_map    = (const float*)d_in[2];
    const float* cls      = (const float*)d_in[3];
    const float* pos      = (const float*)d_in[4];
    const float* ln1_g    = (const float*)d_in[5];
    const float* ln1_b    = (const float*)d_in[6];
    const float* Wq       = (const float*)d_in[7];
    const float* bq       = (const float*)d_in[8];
    const float* Wk       = (const float*)d_in[9];
    const float* bk       = (const float*)d_in[10];
    const float* Wv       = (const float*)d_in[11];
    const float* bv       = (const float*)d_in[12];
    const float* ln2_g    = (const float*)d_in[13];
    const float* ln2_b    = (const float*)d_in[14];
    const float* W1       = (const float*)d_in[15];
    const float* b1       = (const float*)d_in[16];
    const float* W2       = (const float*)d_in[17];
    const float* b2       = (const float*)d_in[18];
    const float* W_head   = (const float*)d_in[19];
    const float* b_head   = (const float*)d_in[20];
    float* out = (float*)d_out;

    float *p_patches, *p_x, *p_h, *p_q, *p_k, *p_v, *p_sc, *p_mlp;
    cudaGetSymbolAddress((void**)&p_patches, g_patches);
    cudaGetSymbolAddress((void**)&p_x, g_x);
    cudaGetSymbolAddress((void**)&p_h, g_h);
    cudaGetSymbolAddress((void**)&p_q, g_q);
    cudaGetSymbolAddress((void**)&p_k, g_k);
    cudaGetSymbolAddress((void**)&p_v, g_v);
    cudaGetSymbolAddress((void**)&p_sc, g_sc);
    cudaGetSymbolAddress((void**)&p_mlp, g_mlp);

    // 1) patchify + embed + assemble
    patchify_kernel<<<(NP * IN_DIM) / 256, 256>>>(images);
    {
        dim3 grid(DMODEL / 128, NP / 128);   // 6 x 49
        sgemm128<0><<<grid, 256>>>(p_patches, W_map, b_map, nullptr, p_mlp,
                                   NP, DMODEL, IN_DIM);
    }
    assemble_kernel<<<(NS * DMODEL) / 256, 256>>>(p_mlp, cls, pos);

    // 2) transformer blocks
    for (int l = 0; l < LAYERS; l++) {
        ln_kernel<<<NS, 256>>>(p_x, ln1_g + l * DMODEL, ln1_b + l * DMODEL, p_h);

        {
            dim3 grid((NS + 63) / 64, NHEAD, 3);
            qkv_kernel<<<grid, 256>>>(p_h,
                Wq + (size_t)l * NHEAD * DHEAD * DHEAD,
                Wk + (size_t)l * NHEAD * DHEAD * DHEAD,
                Wv + (size_t)l * NHEAD * DHEAD * DHEAD,
                bq + (size_t)l * NHEAD * DHEAD,
                bk + (size_t)l * NHEAD * DHEAD,
                bv + (size_t)l * NHEAD * DHEAD,
                p_q, p_k, p_v);
        }
        {
            dim3 grid((SEQ + 63) / 64, (SEQ + 63) / 64, NB * NHEAD);
            scores_kernel<<<grid, 256>>>(p_q, p_k, p_sc);
        }
        softmax_kernel<<<(NB * NHEAD * SEQ) / 8, 256>>>(p_sc);
        {
            dim3 grid((SEQ + 63) / 64, NB * NHEAD);
            av_kernel<<<grid, 256>>>(p_sc, p_v, p_x);
        }

        ln_kernel<<<NS, 256>>>(p_x, ln2_g + l * DMODEL, ln2_b + l * DMODEL, p_h);
        {
            dim3 grid(MLPD / 128, (NS + 127) / 128);   // 24 x 50
            sgemm128<1><<<grid, 256>>>(p_h, W1 + (size_t)l * DMODEL * MLPD,
                                       b1 + (size_t)l * MLPD, nullptr, p_mlp,
                                       NS, MLPD, DMODEL);
        }
        {
            dim3 grid(DMODEL / 128, (NS + 127) / 128); // 6 x 50
            sgemm128<2><<<grid, 256>>>(p_mlp, W2 + (size_t)l * MLPD * DMODEL,
                                       b2 + (size_t)l * DMODEL, p_x, p_x,
                                       NS, DMODEL, MLPD);
        }
    }

    // 3) head + softmax
    head_kernel<<<NB, 256>>>(p_x, W_head, b_head, out);
}

// round 4
// speedup vs baseline: 1.6666x; 1.6666x over previous
#include <cuda_runtime.h>
#include <cuda_bf16.h>
#include <math.h>
#include <cstdint>

// ---------------- problem constants ----------------
#define NB     32
#define SEQ    197
#define DMODEL 768
#define NHEAD  12
#define DHEAD  64
#define LAYERS 12
#define MLPD   3072
#define OUTD   1000
#define PPATCH 196
#define IN_DIM 768
#define NS     (NB * SEQ)       // 6304 tokens
#define NP     (NB * PPATCH)    // 6272 patches
#define SP     200              // padded score row stride

// ---------------- device scratch ----------------
__device__ float g_patches[NP * IN_DIM];
__device__ float g_x[NS * DMODEL];
__device__ float g_h[NS * DMODEL];
__device__ float g_q[NS * DMODEL];
__device__ float g_k[NS * DMODEL];
__device__ float g_v[NS * DMODEL];
__device__ float g_sc[NB * NHEAD * SEQ * SP];
__device__ float g_mlp[NS * MLPD];

__device__ __forceinline__ float tf32r(float x)
{
    float r;
    asm("cvt.rna.tf32.f32 %0, %1;" : "=f"(r) : "f"(x));
    return r;
}

// ---------------- patchify ----------------
__global__ void __launch_bounds__(256)
patchify_kernel(const float* __restrict__ img)
{
    int idx = blockIdx.x * 256 + threadIdx.x;
    if (idx >= NP * IN_DIM) return;
    int t = idx / IN_DIM;
    int e = idx - t * IN_DIM;
    int n = t / PPATCH;
    int p = t - n * PPATCH;
    int py = p / 14, px = p - py * 14;
    int c  = e >> 8;
    int r  = e & 255;
    int ph = r >> 4, pw = r & 15;
    g_patches[idx] = img[(((size_t)n * 3 + c) * 224 + (py * 16 + ph)) * 224 + px * 16 + pw];
}

// ---------------- assemble ----------------
__global__ void __launch_bounds__(256)
assemble_kernel(const float* __restrict__ tokens, const float* __restrict__ cls,
                const float* __restrict__ pos)
{
    int idx = blockIdx.x * 256 + threadIdx.x;
    if (idx >= NS * DMODEL) return;
    int t = idx / DMODEL;
    int d = idx - t * DMODEL;
    int n = t / SEQ;
    int s = t - n * SEQ;
    float v = (s == 0) ? cls[d] : tokens[((size_t)(n * PPATCH + s - 1)) * DMODEL + d];
    g_x[idx] = v + pos[s * DMODEL + d];
}

// ---------------- tf32 tensor-core GEMM: C = A@B + bias (+epilogue) ----------------
// Block 128x128, BK=32, 256 threads = 8 warps, warp tile 32(M) x 64(N).
// EPI: 0 = bias, 1 = bias + exact GELU, 2 = bias + residual add
template<int EPI>
__global__ void __launch_bounds__(256)
tgemm128(const float* __restrict__ A, const float* __restrict__ B,
         const float* __restrict__ bias, const float* __restrict__ res,
         float* __restrict__ C, int M, int N, int K)
{
    __shared__ float As[32][132];   // [k][m], +4 pad
    __shared__ float Bs[32][132];   // [k][n], +4 pad

    const int tid  = threadIdx.x;
    const int wid  = tid >> 5;
    const int lane = tid & 31;
    const int g    = lane >> 2;     // groupID 0..7
    const int tig  = lane & 3;      // thread-in-group 0..3
    const int mw   = wid & 3;       // warp M index (4)
    const int nw   = wid >> 2;      // warp N index (2)
    const int bm   = blockIdx.y * 128;
    const int bn   = blockIdx.x * 128;

    float acc[2][8][4];
    #pragma unroll
    for (int i = 0; i < 2; i++)
        #pragma unroll
        for (int j = 0; j < 8; j++)
            #pragma unroll
            for (int c = 0; c < 4; c++) acc[i][j][c] = 0.f;

    for (int k0 = 0; k0 < K; k0 += 32) {
        // load A tile 128x32 -> As[k][m]
        #pragma unroll
        for (int p = 0; p < 4; p++) {
            int idx = p * 256 + tid;
            int m   = idx >> 3;          // 0..127
            int k4  = (idx & 7) * 4;     // 0..28
            float4 v = make_float4(0.f, 0.f, 0.f, 0.f);
            if (bm + m < M)
                v = *(const float4*)(A + (size_t)(bm + m) * K + k0 + k4);
            As[k4 + 0][m] = tf32r(v.x);
            As[k4 + 1][m] = tf32r(v.y);
            As[k4 + 2][m] = tf32r(v.z);
            As[k4 + 3][m] = tf32r(v.w);
        }
        // load B tile 32x128 -> Bs[k][n]
        #pragma unroll
        for (int p = 0; p < 4; p++) {
            int idx = p * 256 + tid;
            int k   = idx >> 5;          // 0..31
            int n4  = (idx & 31) * 4;    // 0..124
            float4 v = *(const float4*)(B + (size_t)(k0 + k) * N + bn + n4);
            float4 w;
            w.x = tf32r(v.x); w.y = tf32r(v.y); w.z = tf32r(v.z); w.w = tf32r(v.w);
            *(float4*)&Bs[k][n4] = w;
        }
        __syncthreads();

        #pragma unroll
        for (int ks = 0; ks < 4; ks++) {
            const int kk = ks * 8;
            // A fragments: 2 m-tiles
            uint32_t af[2][4];
            #pragma unroll
            for (int mt = 0; mt < 2; mt++) {
                int rb = mw * 32 + mt * 16;
                af[mt][0] = __float_as_uint(As[kk + tig]    [rb + g]);
                af[mt][1] = __float_as_uint(As[kk + tig]    [rb + g + 8]);
                af[mt][2] = __float_as_uint(As[kk + tig + 4][rb + g]);
                af[mt][3] = __float_as_uint(As[kk + tig + 4][rb + g + 8]);
            }
            // B fragments: 8 n-tiles
            uint32_t bf[8][2];
            #pragma unroll
            for (int nt = 0; nt < 8; nt++) {
                int cb = nw * 64 + nt * 8 + g;
                bf[nt][0] = __float_as_uint(Bs[kk + tig]    [cb]);
                bf[nt][1] = __float_as_uint(Bs[kk + tig + 4][cb]);
            }
            #pragma unroll
            for (int mt = 0; mt < 2; mt++)
                #pragma unroll
                for (int nt = 0; nt < 8; nt++) {
                    asm volatile(
                        "mma.sync.aligned.m16n8k8.row.col.f32.tf32.tf32.f32 "
                        "{%0,%1,%2,%3},{%4,%5,%6,%7},{%8,%9},{%0,%1,%2,%3};"
                        : "+f"(acc[mt][nt][0]), "+f"(acc[mt][nt][1]),
                          "+f"(acc[mt][nt][2]), "+f"(acc[mt][nt][3])
                        : "r"(af[mt][0]), "r"(af[mt][1]), "r"(af[mt][2]), "r"(af[mt][3]),
                          "r"(bf[nt][0]), "r"(bf[nt][1]));
                }
        }
        __syncthreads();
    }

    // epilogue
    #pragma unroll
    for (int mt = 0; mt < 2; mt++) {
        int r0 = bm + mw * 32 + mt * 16 + g;
        int r1 = r0 + 8;
        #pragma unroll
        for (int nt = 0; nt < 8; nt++) {
            int c0 = bn + nw * 64 + nt * 8 + 2 * tig;
            float b0 = bias[c0], b1 = bias[c0 + 1];
            #pragma unroll
            for (int half = 0; half < 2; half++) {
                int row = half ? r1 : r0;
                if (row >= M) continue;
                float v0 = acc[mt][nt][half * 2 + 0] + b0;
                float v1 = acc[mt][nt][half * 2 + 1] + b1;
                if (EPI == 1) {
                    v0 = 0.5f * v0 * (1.f + erff(v0 * 0.70710678118654752f));
                    v1 = 0.5f * v1 * (1.f + erff(v1 * 0.70710678118654752f));
                }
                if (EPI == 2) {
                    const float2 rr = *(const float2*)(res + (size_t)row * N + c0);
                    v0 += rr.x; v1 += rr.y;
                }
                float2 o; o.x = v0; o.y = v1;
                *(float2*)(C + (size_t)row * N + c0) = o;
            }
        }
    }
}

// ---------------- LayerNorm ----------------
__global__ void __launch_bounds__(256)
ln_kernel(const float* __restrict__ x, const float* __restrict__ g,
          const float* __restrict__ b, float* __restrict__ o)
{
    int row = blockIdx.x;
    int tid = threadIdx.x;
    const float* xr = x + (size_t)row * DMODEL;
    float v0 = xr[tid], v1 = xr[tid + 256], v2 = xr[tid + 512];

    __shared__ float red[10];
    float s = v0 + v1 + v2;
    #pragma unroll
    for (int of = 16; of; of >>= 1) s += __shfl_xor_sync(~0u, s, of);
    if ((tid & 31) == 0) red[tid >> 5] = s;
    __syncthreads();
    if (tid == 0) {
        float t = 0.f;
        #pragma unroll
        for (int i = 0; i < 8; i++) t += red[i];
        red[8] = t * (1.f / 768.f);
    }
    __syncthreads();
    float mu = red[8];
    float d0 = v0 - mu, d1 = v1 - mu, d2 = v2 - mu;
    float q = d0 * d0 + d1 * d1 + d2 * d2;
    #pragma unroll
    for (int of = 16; of; of >>= 1) q += __shfl_xor_sync(~0u, q, of);
    if ((tid & 31) == 0) red[tid >> 5] = q;
    __syncthreads();
    if (tid == 0) {
        float t = 0.f;
        #pragma unroll
        for (int i = 0; i < 8; i++) t += red[i];
        red[9] = rsqrtf(t * (1.f / 768.f) + 1e-5f);
    }
    __syncthreads();
    float inv = red[9];
    float* orow = o + (size_t)row * DMODEL;
    orow[tid]       = d0 * inv * g[tid]       + b[tid];
    orow[tid + 256] = d1 * inv * g[tid + 256] + b[tid + 256];
    orow[tid + 512] = d2 * inv * g[tid + 512] + b[tid + 512];
}

// ---------------- per-head QKV projection ----------------
__global__ void __launch_bounds__(256)
qkv_kernel(const float* __restrict__ h,
           const float* __restrict__ Wq, const float* __restrict__ Wk, const float* __restrict__ Wv,
           const float* __restrict__ bq, const float* __restrict__ bk, const float* __restrict__ bv,
           float* __restrict__ q, float* __restrict__ k, float* __restrict__ v)
{
    int t0 = blockIdx.x * 64;
    int hh = blockIdx.y;
    int z  = blockIdx.z;
    const float* W  = (z == 0) ? Wq : (z == 1) ? Wk : Wv;
    const float* bb = (z == 0) ? bq : (z == 1) ? bk : bv;
    float* out      = (z == 0) ? q  : (z == 1) ? k  : v;
    W  += hh * 64 * 64;
    bb += hh * 64;

    __shared__ float Xs[64][64];
    __shared__ float Ws[64][64];
    int tid = threadIdx.x;
    #pragma unroll
    for (int r = 0; r < 4; r++) {
        int row = (tid >> 4) + r * 16;
        int col = (tid & 15) * 4;
        int tok = t0 + row;
        float4 xv = make_float4(0.f, 0.f, 0.f, 0.f);
        if (tok < NS) xv = *(const float4*)(h + (size_t)tok * DMODEL + hh * 64 + col);
        Xs[col + 0][row] = xv.x; Xs[col + 1][row] = xv.y;
        Xs[col + 2][row] = xv.z; Xs[col + 3][row] = xv.w;
        float4 wv = *(const float4*)(W + row * 64 + col);
        Ws[row][col + 0] = wv.x; Ws[row][col + 1] = wv.y;
        Ws[row][col + 2] = wv.z; Ws[row][col + 3] = wv.w;
    }
    __syncthreads();

    int trr = (tid >> 4) * 4;
    int tcc = (tid & 15) * 4;
    float acc[4][4] = {};
    #pragma unroll
    for (int d = 0; d < 64; d++) {
        float ra[4], rb[4];
        #pragma unroll
        for (int i = 0; i < 4; i++) ra[i] = Xs[d][trr + i];
        #pragma unroll
        for (int j = 0; j < 4; j++) rb[j] = Ws[d][tcc + j];
        #pragma unroll
        for (int i = 0; i < 4; i++)
            #pragma unroll
            for (int j = 0; j < 4; j++)
                acc[i][j] = fmaf(ra[i], rb[j], acc[i][j]);
    }
    #pragma unroll
    for (int i = 0; i < 4; i++) {
        int tok = t0 + trr + i;
        if (tok >= NS) continue;
        #pragma unroll
        for (int j = 0; j < 4; j++)
            out[(size_t)tok * DMODEL + hh * 64 + tcc + j] = acc[i][j] + bb[tcc + j];
    }
}

// ---------------- scores = Q K^T / 8 ----------------
__global__ void __launch_bounds__(256)
scores_kernel(const float* __restrict__ q, const float* __restrict__ k,
              float* __restrict__ sc)
{
    int q0 = blockIdx.x * 64;
    int k0 = blockIdx.y * 64;
    int b  = blockIdx.z;
    int n  = b / NHEAD, hh = b - n * NHEAD;

    __shared__ float Qs[64][64];
    __shared__ float Ks[64][64];
    int tid = threadIdx.x;
    #pragma unroll
    for (int r = 0; r < 4; r++) {
        int row = (tid >> 4) + r * 16;
        int col = (tid & 15) * 4;
        int qt = q0 + row, kt = k0 + row;
        float4 qv = make_float4(0.f, 0.f, 0.f, 0.f);
        float4 kv = make_float4(0.f, 0.f, 0.f, 0.f);
        if (qt < SEQ) qv = *(const float4*)(q + (size_t)(n * SEQ + qt) * DMODEL + hh * 64 + col);
        if (kt < SEQ) kv = *(const float4*)(k + (size_t)(n * SEQ + kt) * DMODEL + hh * 64 + col);
        Qs[col + 0][row] = qv.x; Qs[col + 1][row] = qv.y;
        Qs[col + 2][row] = qv.z; Qs[col + 3][row] = qv.w;
        Ks[col + 0][row] = kv.x; Ks[col + 1][row] = kv.y;
        Ks[col + 2][row] = kv.z; Ks[col + 3][row] = kv.w;
    }
    __syncthreads();

    int tr = (tid >> 4) * 4;
    int tc = (tid & 15) * 4;
    float acc[4][4] = {};
    #pragma unroll
    for (int e = 0; e < 64; e++) {
        float ra[4], rb[4];
        #pragma unroll
        for (int i = 0; i < 4; i++) ra[i] = Qs[e][tr + i];
        #pragma unroll
        for (int j = 0; j < 4; j++) rb[j] = Ks[e][tc + j];
        #pragma unroll
        for (int i = 0; i < 4; i++)
            #pragma unroll
            for (int j = 0; j < 4; j++)
                acc[i][j] = fmaf(ra[i], rb[j], acc[i][j]);
    }
    #pragma unroll
    for (int i = 0; i < 4; i++) {
        int qi = q0 + tr + i;
        if (qi >= SEQ) continue;
        #pragma unroll
        for (int j = 0; j < 4; j++) {
            int kj = k0 + tc + j;
            if (kj < SEQ)
                sc[((size_t)b * SEQ + qi) * SP + kj] = acc[i][j] * 0.125f;
        }
    }
}

// ---------------- softmax ----------------
__global__ void __launch_bounds__(256)
softmax_kernel(float* __restrict__ sc)
{
    int warp = (blockIdx.x * 256 + threadIdx.x) >> 5;
    int lane = threadIdx.x & 31;
    if (warp >= NB * NHEAD * SEQ) return;
    float* row = sc + (size_t)warp * SP;

    float mx = -1e30f;
    for (int i = lane; i < SEQ; i += 32) mx = fmaxf(mx, row[i]);
    #pragma unroll
    for (int of = 16; of; of >>= 1) mx = fmaxf(mx, __shfl_xor_sync(~0u, mx, of));

    float sum = 0.f;
    for (int i = lane; i < SEQ; i += 32) {
        float e = expf(row[i] - mx);
        row[i] = e;
        sum += e;
    }
    #pragma unroll
    for (int of = 16; of; of >>= 1) sum += __shfl_xor_sync(~0u, sum, of);
    float inv = 1.f / sum;
    for (int i = lane; i < SEQ; i += 32) row[i] *= inv;
}

// ---------------- O = attn @ V (+residual) ----------------
__global__ void __launch_bounds__(256)
av_kernel(const float* __restrict__ sc, const float* __restrict__ v,
          float* __restrict__ x)
{
    int q0 = blockIdx.x * 64;
    int b  = blockIdx.y;
    int n  = b / NHEAD, hh = b - n * NHEAD;

    __shared__ float As[64][64];
    __shared__ float Vs[64][64];
    int tid = threadIdx.x;
    int tr = (tid >> 4) * 4;
    int tc = (tid & 15) * 4;
    float acc[4][4] = {};

    for (int k0 = 0; k0 < SEQ; k0 += 64) {
        #pragma unroll
        for (int r = 0; r < 4; r++) {
            int row = (tid >> 4) + r * 16;
            int col = (tid & 15) * 4;
            float4 avv = make_float4(0.f, 0.f, 0.f, 0.f);
            int qt = q0 + row;
            if (qt < SEQ) {
                const float* p = sc + ((size_t)b * SEQ + qt) * SP + k0 + col;
                if (k0 + col + 3 < SEQ) {
                    avv = *(const float4*)p;
                } else {
                    if (k0 + col + 0 < SEQ) avv.x = p[0];
                    if (k0 + col + 1 < SEQ) avv.y = p[1];
                    if (k0 + col + 2 < SEQ) avv.z = p[2];
                }
            }
            As[col + 0][row] = avv.x; As[col + 1][row] = avv.y;
            As[col + 2][row] = avv.z; As[col + 3][row] = avv.w;
            float4 vv = make_float4(0.f, 0.f, 0.f, 0.f);
            int kt = k0 + row;
            if (kt < SEQ) vv = *(const float4*)(v + (size_t)(n * SEQ + kt) * DMODEL + hh * 64 + col);
            Vs[row][col + 0] = vv.x; Vs[row][col + 1] = vv.y;
            Vs[row][col + 2] = vv.z; Vs[row][col + 3] = vv.w;
        }
        __syncthreads();
        #pragma unroll
        for (int kk = 0; kk < 64; kk++) {
            float ra[4], rb[4];
            #pragma unroll
            for (int i = 0; i < 4; i++) ra[i] = As[kk][tr + i];
            #pragma unroll
            for (int j = 0; j < 4; j++) rb[j] = Vs[kk][tc + j];
            #pragma unroll
            for (int i = 0; i < 4; i++)
                #pragma unroll
                for (int j = 0; j < 4; j++)
                    acc[i][j] = fmaf(ra[i], rb[j], acc[i][j]);
        }
        __syncthreads();
    }
    #pragma unroll
    for (int i = 0; i < 4; i++) {
        int qi = q0 + tr + i;
        if (qi >= SEQ) continue;
        #pragma unroll
        for (int j = 0; j < 4; j++) {
            size_t idx = (size_t)(n * SEQ + qi) * DMODEL + hh * 64 + tc + j;
            x[idx] += acc[i][j];
        }
    }
}

// ---------------- head + softmax ----------------
__global__ void __launch_bounds__(256)
head_kernel(const float* __restrict__ x, const float* __restrict__ Wh,
            const float* __restrict__ bh, float* __restrict__ out)
{
    __shared__ float xs[DMODEL];
    __shared__ float lg[OUTD];
    __shared__ float red[256];
    int n = blockIdx.x, tid = threadIdx.x;
    for (int i = tid; i < DMODEL; i += 256) xs[i] = x[(size_t)n * SEQ * DMODEL + i];
    __syncthreads();
    for (int o = tid; o < OUTD; o += 256) {
        float a = bh[o];
        for (int kk = 0; kk < DMODEL; kk++)
            a = fmaf(xs[kk], Wh[(size_t)kk * OUTD + o], a);
        lg[o] = a;
    }
    __syncthreads();
    float m = -1e30f;
    for (int o = tid; o < OUTD; o += 256) m = fmaxf(m, lg[o]);
    red[tid] = m; __syncthreads();
    for (int s = 128; s; s >>= 1) { if (tid < s) red[tid] = fmaxf(red[tid], red[tid + s]); __syncthreads(); }
    float mx = red[0]; __syncthreads();
    float sm = 0.f;
    for (int o = tid; o < OUTD; o += 256) sm += expf(lg[o] - mx);
    red[tid] = sm; __syncthreads();
    for (int s = 128; s; s >>= 1) { if (tid < s) red[tid] += red[tid + s]; __syncthreads(); }
    float inv = 1.f / red[0];
    __syncthreads();
    for (int o = tid; o < OUTD; o += 256)
        out[(size_t)n * OUTD + o] = expf(lg[o] - mx) * inv;
}

// ---------------- host orchestration ----------------
extern "C" void kernel_launch(void* const* d_in, const int* in_sizes, int n_in,
                              void* d_out, int out_size)
{
    const float* images   = (const float*)d_in[0];
    const float* W_map    = (const float*)d_in[1];
    const float* b_map    = (const float*)d_in[2];
    const float* cls      = (const float*)d_in[3];
    const float* pos      = (const float*)d_in[4];
    const float* ln1_g    = (const float*)d_in[5];
    const float* ln1_b    = (const float*)d_in[6];
    const float* Wq       = (const float*)d_in[7];
    const float* bq       = (const float*)d_in[8];
    const float* Wk       = (const float*)d_in[9];
    const float* bk       = (const float*)d_in[10];
    const float* Wv       = (const float*)d_in[11];
    const float* bv       = (const float*)d_in[12];
    const float* ln2_g    = (const float*)d_in[13];
    const float* ln2_b    = (const float*)d_in[14];
    const float* W1       = (const float*)d_in[15];
    const float* b1       = (const float*)d_in[16];
    const float* W2       = (const float*)d_in[17];
    const float* b2       = (const float*)d_in[18];
    const float* W_head   = (const float*)d_in[19];
    const float* b_head   = (const float*)d_in[20];
    float* out = (float*)d_out;

    float *p_patches, *p_x, *p_h, *p_q, *p_k, *p_v, *p_sc, *p_mlp;
    cudaGetSymbolAddress((void**)&p_patches, g_patches);
    cudaGetSymbolAddress((void**)&p_x, g_x);
    cudaGetSymbolAddress((void**)&p_h, g_h);
    cudaGetSymbolAddress((void**)&p_q, g_q);
    cudaGetSymbolAddress((void**)&p_k, g_k);
    cudaGetSymbolAddress((void**)&p_v, g_v);
    cudaGetSymbolAddress((void**)&p_sc, g_sc);
    cudaGetSymbolAddress((void**)&p_mlp, g_mlp);

    // 1) patchify + embed + assemble
    patchify_kernel<<<(NP * IN_DIM) / 256, 256>>>(images);
    {
        dim3 grid(DMODEL / 128, NP / 128);   // 6 x 49
        tgemm128<0><<<grid, 256>>>(p_patches, W_map, b_map, nullptr, p_mlp,
                                   NP, DMODEL, IN_DIM);
    }
    assemble_kernel<<<(NS * DMODEL) / 256, 256>>>(p_mlp, cls, pos);

    // 2) transformer blocks
    for (int l = 0; l < LAYERS; l++) {
        ln_kernel<<<NS, 256>>>(p_x, ln1_g + l * DMODEL, ln1_b + l * DMODEL, p_h);

        {
            dim3 grid((NS + 63) / 64, NHEAD, 3);
            qkv_kernel<<<grid, 256>>>(p_h,
                Wq + (size_t)l * NHEAD * DHEAD * DHEAD,
                Wk + (size_t)l * NHEAD * DHEAD * DHEAD,
                Wv + (size_t)l * NHEAD * DHEAD * DHEAD,
                bq + (size_t)l * NHEAD * DHEAD,
                bk + (size_t)l * NHEAD * DHEAD,
                bv + (size_t)l * NHEAD * DHEAD,
                p_q, p_k, p_v);
        }
        {
            dim3 grid((SEQ + 63) / 64, (SEQ + 63) / 64, NB * NHEAD);
            scores_kernel<<<grid, 256>>>(p_q, p_k, p_sc);
        }
        softmax_kernel<<<(NB * NHEAD * SEQ) / 8, 256>>>(p_sc);
        {
            dim3 grid((SEQ + 63) / 64, NB * NHEAD);
            av_kernel<<<grid, 256>>>(p_sc, p_v, p_x);
        }

        ln_kernel<<<NS, 256>>>(p_x, ln2_g + l * DMODEL, ln2_b + l * DMODEL, p_h);
        {
            dim3 grid(MLPD / 128, (NS + 127) / 128);   // 24 x 50
            tgemm128<1><<<grid, 256>>>(p_h, W1 + (size_t)l * DMODEL * MLPD,
                                       b1 + (size_t)l * MLPD, nullptr, p_mlp,
                                       NS, MLPD, DMODEL);
        }
        {
            dim3 grid(DMODEL / 128, (NS + 127) / 128); // 6 x 50
            tgemm128<2><<<grid, 256>>>(p_mlp, W2 + (size_t)l * MLPD * DMODEL,
                                       b2 + (size_t)l * DMODEL, p_x, p_x,
                                       NS, DMODEL, MLPD);
        }
    }

    // 3) head + softmax
    head_kernel<<<NB, 256>>>(p_x, W_head, b_head, out);
}